// round 2
// baseline (speedup 1.0000x reference)
#include <cuda_runtime.h>
#include <math.h>

#define Bz 16
#define C 256
#define H 48
#define W 160
#define HW (H*W)            // 7680
#define CHW (C*HW)          // 1966080

// Scratch (no allocations allowed -> __device__ globals)
__device__ float g_disp[Bz*HW];                       // 0.5 MB
__device__ float g_M[(size_t)Bz*C*HW];                // 126 MB

// ---------------------------------------------------------------------------
// Kernel 1: 3x3x256 -> 1 conv, tanh, *0.1  (disp field)
// Rewritten as 9 channel-reductions G_j[y,x] = sum_c w[c,j]*f[c,y,x],
// then d[y,x] = sum_{dy,dx} G_{(dy,dx)}[y+dy, x+dx]. Streams features once.
// ---------------------------------------------------------------------------
#define CONV_R 6   // output rows per block; block covers CONV_R+2 rows x 160
__global__ void conv_kernel(const float* __restrict__ f,
                            const float* __restrict__ w_disp,
                            const float* __restrict__ b_disp)
{
    __shared__ float sG[9 * 8 * W];   // 9 * 1280 floats = 46 KB
    const int b  = blockIdx.y;
    const int r0 = blockIdx.x * CONV_R;
    const int tid = threadIdx.x;
    const float* Fb = f + (size_t)b * CHW;

    // 8 rows (incl. halo) x 160 cols = 1280 positions, 5 per thread
    int  off[5];
    bool valid[5];
    float acc[5][9];
    #pragma unroll
    for (int i = 0; i < 5; i++) {
        int p  = tid + i * 256;
        int gr = r0 - 1 + p / W;
        int gx = p % W;
        valid[i] = (gr >= 0 && gr < H);
        off[i]   = gr * W + gx;
        #pragma unroll
        for (int j = 0; j < 9; j++) acc[i][j] = 0.f;
    }

    for (int c = 0; c < C; c++) {
        float wv[9];
        #pragma unroll
        for (int j = 0; j < 9; j++) wv[j] = __ldg(&w_disp[c*9 + j]);   // uniform, L1-hot
        const float* fc = Fb + (size_t)c * HW;
        #pragma unroll
        for (int i = 0; i < 5; i++) {
            float v = valid[i] ? __ldg(&fc[off[i]]) : 0.f;
            #pragma unroll
            for (int j = 0; j < 9; j++) acc[i][j] += wv[j] * v;
        }
    }

    #pragma unroll
    for (int i = 0; i < 5; i++) {
        int p = tid + i * 256;
        #pragma unroll
        for (int j = 0; j < 9; j++) sG[j*(8*W) + p] = acc[i][j];
    }
    __syncthreads();

    const float bd = __ldg(&b_disp[0]);
    for (int q = tid; q < CONV_R * W; q += 256) {
        int qr = q / W, ox = q % W;
        float s = 0.f;
        #pragma unroll
        for (int dy = -1; dy <= 1; dy++)
            #pragma unroll
            for (int dx = -1; dx <= 1; dx++) {
                int xx = ox + dx;
                if (xx >= 0 && xx < W) {
                    int j = (dy+1)*3 + (dx+1);
                    s += sG[j*(8*W) + (qr+1+dy)*W + xx];
                }
            }
        g_disp[b*HW + (r0+qr)*W + ox] = 0.1f * tanhf(s + bd);
    }
}

// ---------------------------------------------------------------------------
// Kernel 2: per-batch dense GEMM  M[b,o,:] = sum_c w_ext[o, 1+c] * f[b,c,:]
// (sampling commutes with channel mixing, so GEMM runs on un-sampled f)
// Block tile 64(M=o) x 128(N=px), K-chunk 16, 4x8 micro-tile per thread.
// ---------------------------------------------------------------------------
#define BM 64
#define BN 128
#define BK 16
__global__ void gemm_kernel(const float* __restrict__ f,
                            const float* __restrict__ w_ext)
{
    __shared__ float As[BM][BK];
    __shared__ float Bs[BK][BN];

    const int b  = blockIdx.z;
    const int m0 = blockIdx.y * BM;
    const int n0 = blockIdx.x * BN;
    const float* Fb = f   + (size_t)b * CHW;
    float*       Mo = g_M + (size_t)b * CHW;

    const int tid = threadIdx.x;
    const int tm  = tid / 16;      // 0..15  -> m = m0 + tm*4 + i
    const int tn  = tid % 16;      // 0..15  -> n = n0 + tn*8 + j

    float acc[4][8];
    #pragma unroll
    for (int i = 0; i < 4; i++)
        #pragma unroll
        for (int j = 0; j < 8; j++) acc[i][j] = 0.f;

    const int la_m = tid & 63;          // As: 64 rows, 4 contiguous k each
    const int la_k = (tid >> 6) * 4;
    const int lb_k = tid >> 4;          // Bs: 16 rows, 8 contiguous n each
    const int lb_n = (tid & 15) * 8;

    for (int k0 = 0; k0 < C; k0 += BK) {
        const float* wp = w_ext + (size_t)(m0 + la_m) * 257 + 1 + k0 + la_k;
        #pragma unroll
        for (int t = 0; t < 4; t++) As[la_m][la_k + t] = __ldg(&wp[t]);

        const float* fp = Fb + (size_t)(k0 + lb_k) * HW + n0 + lb_n;
        float4 v0 = *(const float4*)fp;
        float4 v1 = *(const float4*)(fp + 4);
        *(float4*)&Bs[lb_k][lb_n]     = v0;
        *(float4*)&Bs[lb_k][lb_n + 4] = v1;
        __syncthreads();

        #pragma unroll
        for (int k = 0; k < BK; k++) {
            float a[4];
            #pragma unroll
            for (int i = 0; i < 4; i++) a[i] = As[tm*4 + i][k];
            float4 b0 = *(float4*)&Bs[k][tn*8];
            float4 b1 = *(float4*)&Bs[k][tn*8 + 4];
            float bb[8] = {b0.x,b0.y,b0.z,b0.w,b1.x,b1.y,b1.z,b1.w};
            #pragma unroll
            for (int i = 0; i < 4; i++)
                #pragma unroll
                for (int j = 0; j < 8; j++) acc[i][j] += a[i] * bb[j];
        }
        __syncthreads();
    }

    #pragma unroll
    for (int i = 0; i < 4; i++) {
        float* op = Mo + (size_t)(m0 + tm*4 + i) * HW + n0 + tn*8;
        *(float4*)op       = make_float4(acc[i][0], acc[i][1], acc[i][2], acc[i][3]);
        *(float4*)(op + 4) = make_float4(acc[i][4], acc[i][5], acc[i][6], acc[i][7]);
    }
}

// ---------------------------------------------------------------------------
// Kernel 3: fused sampling epilogue.
// gy from closed-form y_shifts_base + disp; vertical 2-tap lerp of M and of
// the analytic disparity channel; + bias, residual, relu.
// ---------------------------------------------------------------------------
__global__ void epilogue_kernel(const float* __restrict__ f,
                                const float* __restrict__ P2,
                                const float* __restrict__ w_ext,
                                const float* __restrict__ b_ext,
                                const float* __restrict__ alpha,
                                float* __restrict__ out)
{
    const size_t idx = (size_t)blockIdx.x * blockDim.x + threadIdx.x;
    const int x = (int)(idx % W);
    const int y = (int)((idx / W) % H);
    const int o = (int)((idx / HW) % C);
    const int b = (int)(idx / ((size_t)C * HW));

    // P2 row 1 (indices 4..7) divided by 16
    const float fyv = __ldg(&P2[b*12 + 5]) * 0.0625f;
    const float cyv = __ldg(&P2[b*12 + 6]) * 0.0625f;
    const float Tyv = __ldg(&P2[b*12 + 7]) * 0.0625f;
    const float denom = fabsf(fyv * 1.65f + Tyv) + 1e-10f;

    const float dval = g_disp[b*HW + y*W + x];
    const float yf = (float)y;
    // y_shifts_base = relu(1.535*(y-cy)/(2*(1.65-0.5*1.535))) / (H*0.5)
    const float ysb   = fmaxf(1.535f * (yf - cyv) / (2.f * (1.65f - 0.5f * 1.535f)), 0.f) * (1.f/24.f);
    const float ybase = -1.f + yf * (2.f / 47.f);
    const float gy = ybase + ysb + dval;

    float iy  = fminf(fmaxf((gy + 1.f) * 0.5f * 47.f, 0.f), 47.f);
    float y0f = floorf(iy);
    float wy  = iy - y0f;
    int y0 = (int)y0f;
    int y1 = min(y0 + 1, H - 1);

    // analytic disparity channel (channel 0 of feats), constant over x
    const float sc = fyv * 0.54f / denom;
    float d0 = fmaxf(sc * (y0f - cyv), 0.f);
    float d1 = fmaxf(sc * ((float)y1 - cyv), 0.f);
    float samp0 = d0 + wy * (d1 - d0);

    const float* Mb = g_M + ((size_t)b * C + o) * HW;
    float m0v = Mb[y0*W + x];
    float m1v = Mb[y1*W + x];
    float mval = m0v + wy * (m1v - m0v);

    float val = __ldg(&w_ext[o*257]) * samp0 + mval + __ldg(&b_ext[o]);
    out[idx] = fmaxf(f[idx] + val * __ldg(&alpha[0]), 0.f);
}

// ---------------------------------------------------------------------------
extern "C" void kernel_launch(void* const* d_in, const int* in_sizes, int n_in,
                              void* d_out, int out_size)
{
    const float* features = (const float*)d_in[0];
    const float* P2       = (const float*)d_in[1];
    const float* w_disp   = (const float*)d_in[2];
    const float* b_disp   = (const float*)d_in[3];
    const float* w_ext    = (const float*)d_in[4];
    const float* b_ext    = (const float*)d_in[5];
    const float* alpha    = (const float*)d_in[6];
    float* out = (float*)d_out;

    conv_kernel<<<dim3(H / CONV_R, Bz), 256>>>(features, w_disp, b_disp);
    gemm_kernel<<<dim3(HW / BN, C / BM, Bz), 256>>>(features, w_ext);

    const long long total = (long long)Bz * C * HW;   // 31,457,280
    epilogue_kernel<<<(unsigned)(total / 256), 256>>>(features, P2, w_ext, b_ext, alpha, out);
}

// round 3
// speedup vs baseline: 1.4804x; 1.4804x over previous
#include <cuda_runtime.h>
#include <math.h>

#define Bz 16
#define C 256
#define H 48
#define W 160
#define HW (H*W)            // 7680
#define CHW (C*HW)          // 1966080

typedef unsigned long long ull;

// Scratch (__device__ globals; no allocations allowed)
__device__ float g_G[(size_t)Bz * 9 * HW];   // 4.4 MB  per-pixel channel reductions
__device__ int   g_y0[Bz * HW];
__device__ float g_wy[Bz * HW];
__device__ float g_samp0[Bz * HW];

// ---- packed f32x2 helpers (Blackwell FFMA2 path) -------------------------
__device__ __forceinline__ void fma2(ull& d, ull a, ull b) {
    asm("fma.rn.f32x2 %0, %1, %2, %0;" : "+l"(d) : "l"(a), "l"(b));
}
__device__ __forceinline__ ull pack2(float lo, float hi) {
    ull r; asm("mov.b64 %0, {%1, %2};" : "=l"(r) : "f"(lo), "f"(hi)); return r;
}
__device__ __forceinline__ void unpack2(float& lo, float& hi, ull v) {
    asm("mov.b64 {%0, %1}, %2;" : "=f"(lo), "=f"(hi) : "l"(v));
}

// ---------------------------------------------------------------------------
// Kernel 1 (conv phase A): G_j[b,p] = sum_c w_disp[c,j] * f[b,c,p]
// Each thread owns 2 adjacent pixels (packed f32x2). Streams features once.
// grid: (HW/512, Bz) x 256 threads
// ---------------------------------------------------------------------------
__global__ __launch_bounds__(256) void convA_kernel(const float* __restrict__ f,
                                                    const float* __restrict__ w_disp)
{
    __shared__ ull sW2[C * 9];      // pre-splatted weights, 18 KB
    const int tid = threadIdx.x;
    const int b   = blockIdx.y;
    const int p2  = blockIdx.x * 512 + tid * 2;

    for (int i = tid; i < C * 9; i += 256) {
        float w = __ldg(&w_disp[i]);
        sW2[i] = pack2(w, w);
    }
    __syncthreads();

    const float* Fb = f + (size_t)b * CHW;
    ull acc[9];
    #pragma unroll
    for (int j = 0; j < 9; j++) acc[j] = 0ull;

    #pragma unroll 4
    for (int c = 0; c < C; c++) {
        ull v = *(const ull*)&Fb[(size_t)c * HW + p2];
        #pragma unroll
        for (int j = 0; j < 9; j++) fma2(acc[j], sW2[c * 9 + j], v);
    }

    #pragma unroll
    for (int j = 0; j < 9; j++)
        *(ull*)&g_G[((size_t)(b * 9 + j)) * HW + p2] = acc[j];
}

// ---------------------------------------------------------------------------
// Kernel 2 (conv phase B + grid precompute): 3x3 combine of G (zero pad),
// tanh -> disp, then per-pixel sampling params y0/wy and analytic samp0.
// grid: (HW/256, Bz) x 256 threads
// ---------------------------------------------------------------------------
__global__ __launch_bounds__(256) void phaseB_kernel(const float* __restrict__ P2,
                                                     const float* __restrict__ b_disp)
{
    const int b = blockIdx.y;
    const int p = blockIdx.x * 256 + threadIdx.x;
    const int y = p / W, x = p % W;

    float s = 0.f;
    #pragma unroll
    for (int dy = -1; dy <= 1; dy++) {
        int yy = y + dy;
        if (yy < 0 || yy >= H) continue;
        #pragma unroll
        for (int dx = -1; dx <= 1; dx++) {
            int xx = x + dx;
            if (xx >= 0 && xx < W) {
                int j = (dy + 1) * 3 + (dx + 1);
                s += g_G[((size_t)(b * 9 + j)) * HW + yy * W + xx];
            }
        }
    }
    const float dval = 0.1f * tanhf(s + __ldg(&b_disp[0]));

    const float fyv = __ldg(&P2[b * 12 + 5]) * 0.0625f;
    const float cyv = __ldg(&P2[b * 12 + 6]) * 0.0625f;
    const float Tyv = __ldg(&P2[b * 12 + 7]) * 0.0625f;
    const float denom = fabsf(fyv * 1.65f + Tyv) + 1e-10f;

    const float yf    = (float)y;
    const float ysb   = fmaxf(1.535f * (yf - cyv) / (2.f * (1.65f - 0.5f * 1.535f)), 0.f) * (1.f / 24.f);
    const float ybase = -1.f + yf * (2.f / 47.f);
    const float gy    = ybase + ysb + dval;

    float iy  = fminf(fmaxf((gy + 1.f) * 0.5f * 47.f, 0.f), 47.f);
    float y0f = floorf(iy);
    float wy  = iy - y0f;
    int y0 = (int)y0f;
    int y1 = min(y0 + 1, H - 1);

    const float sc = fyv * 0.54f / denom;
    float d0 = fmaxf(sc * (y0f - cyv), 0.f);
    float d1 = fmaxf(sc * ((float)y1 - cyv), 0.f);

    const int gi = b * HW + p;
    g_y0[gi]    = y0;
    g_wy[gi]    = wy;
    g_samp0[gi] = d0 + wy * (d1 - d0);
}

// ---------------------------------------------------------------------------
// Kernel 3: fused sample+GEMM+epilogue.
//   out[b,o,p] = relu(f[b,o,p] + alpha*(w0[o]*samp0[p]
//                    + sum_c w_ext[o,1+c]*lerp(f[b,c,y0(p),x], f[b,c,y1(p),x], wy)
//                    + b_ext[o]))
// Tile: BM=128(o) x BN=128(px) x BK=16, 256 threads, 8x8 micro in f32x2 pairs.
// A stored pre-splatted (each weight duplicated) -> LDS.64 gives the splat.
// Compute columns: 2*tn + 32*t (+0/1) -> conflict-free LDS.64 on B.
// ---------------------------------------------------------------------------
#define BM 128
#define BN 128
#define BK 16
__global__ __launch_bounds__(256, 2) void gemm_fused_kernel(
    const float* __restrict__ f,
    const float* __restrict__ w_ext,
    const float* __restrict__ b_ext,
    const float* __restrict__ alpha,
    float* __restrict__ out)
{
    __shared__ float Asd[BK][2 * BM];   // 16 KB, pre-splatted A
    __shared__ float Bs[BK][BN];        //  8 KB
    __shared__ int   sOff0[BN], sOff1[BN];
    __shared__ float sWy[BN], sSamp[BN];

    const int tid = threadIdx.x;
    const int b   = blockIdx.z;
    const int m0  = blockIdx.y * BM;
    const int n0  = blockIdx.x * BN;
    const float* Fb = f + (size_t)b * CHW;

    // per-pixel sampling params for this N-tile
    if (tid < BN) {
        int p = n0 + tid;
        int y0 = g_y0[b * HW + p];
        int x  = p % W;
        sOff0[tid] = y0 * W + x;
        sOff1[tid] = min(y0 + 1, H - 1) * W + x;
        sWy[tid]   = g_wy[b * HW + p];
        sSamp[tid] = g_samp0[b * HW + p];
    }
    __syncthreads();

    ull acc2[8][4];
    #pragma unroll
    for (int i = 0; i < 8; i++)
        #pragma unroll
        for (int t = 0; t < 4; t++) acc2[i][t] = 0ull;

    const int tm = tid >> 4;        // 0..15 -> rows m0 + tm*8 + i
    const int tn = tid & 15;        // cols  n0 + 2*tn + 32*t + {0,1}

    const int ak = tid >> 4;            // A loader: k row
    const int am = (tid & 15) * 8;      //           8 m's
    const int bk = tid >> 4;            // B loader: k row
    const int bn = (tid & 15) * 8;      //           8 n's

    for (int k0 = 0; k0 < C; k0 += BK) {
        // A: w_ext[(m)(257) + 1 + k], duplicated for splat
        #pragma unroll
        for (int t = 0; t < 8; t++) {
            float w = __ldg(&w_ext[(size_t)(m0 + am + t) * 257 + 1 + k0 + ak]);
            *(ull*)&Asd[ak][2 * (am + t)] = pack2(w, w);
        }
        // B: sampled feature rows (vertical 2-tap lerp)
        const float* fk = Fb + (size_t)(k0 + bk) * HW;
        #pragma unroll
        for (int t = 0; t < 8; t++) {
            int n = bn + t;
            float v0 = __ldg(&fk[sOff0[n]]);
            float v1 = __ldg(&fk[sOff1[n]]);
            Bs[bk][n] = fmaf(sWy[n], v1 - v0, v0);
        }
        __syncthreads();

        #pragma unroll
        for (int k = 0; k < BK; k++) {
            ull a2[8], b2[4];
            #pragma unroll
            for (int i = 0; i < 8; i++)
                a2[i] = *(const ull*)&Asd[k][2 * (tm * 8 + i)];
            #pragma unroll
            for (int t = 0; t < 4; t++)
                b2[t] = *(const ull*)&Bs[k][2 * tn + 32 * t];
            #pragma unroll
            for (int i = 0; i < 8; i++)
                #pragma unroll
                for (int t = 0; t < 4; t++)
                    fma2(acc2[i][t], a2[i], b2[t]);
        }
        __syncthreads();
    }

    // fused epilogue: + w0*samp0 + bias, *alpha, + residual, relu
    const float al = __ldg(&alpha[0]);
    #pragma unroll
    for (int i = 0; i < 8; i++) {
        const int o = m0 + tm * 8 + i;
        const float w0 = __ldg(&w_ext[(size_t)o * 257]);
        const float be = __ldg(&b_ext[o]);
        const float* fo = Fb + (size_t)o * HW + n0;
        float* oo = out + ((size_t)b * C + o) * HW + n0;
        #pragma unroll
        for (int t = 0; t < 4; t++) {
            int col = 2 * tn + 32 * t;
            float lo, hi;
            unpack2(lo, hi, acc2[i][t]);
            float2 fr = *(const float2*)&fo[col];
            float vlo = fr.x + al * (lo + w0 * sSamp[col]     + be);
            float vhi = fr.y + al * (hi + w0 * sSamp[col + 1] + be);
            float2 r;
            r.x = fmaxf(vlo, 0.f);
            r.y = fmaxf(vhi, 0.f);
            *(float2*)&oo[col] = r;
        }
    }
}

// ---------------------------------------------------------------------------
extern "C" void kernel_launch(void* const* d_in, const int* in_sizes, int n_in,
                              void* d_out, int out_size)
{
    const float* features = (const float*)d_in[0];
    const float* P2       = (const float*)d_in[1];
    const float* w_disp   = (const float*)d_in[2];
    const float* b_disp   = (const float*)d_in[3];
    const float* w_ext    = (const float*)d_in[4];
    const float* b_ext    = (const float*)d_in[5];
    const float* alpha    = (const float*)d_in[6];
    float* out = (float*)d_out;

    convA_kernel <<<dim3(HW / 512, Bz), 256>>>(features, w_disp);
    phaseB_kernel<<<dim3(HW / 256, Bz), 256>>>(P2, b_disp);
    gemm_fused_kernel<<<dim3(HW / BN, C / BM, Bz), 256>>>(features, w_ext, b_ext, alpha, out);
}

// round 5
// speedup vs baseline: 2.1395x; 1.4452x over previous
#include <cuda_runtime.h>
#include <math.h>
#include <stdint.h>

#define Bz 16
#define C 256
#define H 48
#define W 160
#define HW (H*W)            // 7680
#define CHW (C*HW)          // 1966080

typedef unsigned long long ull;

// Scratch (__device__ globals; no allocations allowed)
__device__ float g_G[(size_t)Bz * 4 * 9 * HW];   // 17.7 MB partial conv reductions
__device__ int   g_y0[Bz * HW];
__device__ float g_wy[Bz * HW];
__device__ float g_samp0[Bz * HW];
__device__ float g_Aprep[C * C];                 // transposed w_ext[:,1:], tf32-rounded

// ===================== PTX helpers ==============================
__device__ __forceinline__ void fma2(ull& d, ull a, ull b) {
    asm("fma.rn.f32x2 %0, %1, %2, %0;" : "+l"(d) : "l"(a), "l"(b));
}
__device__ __forceinline__ ull pack2(float lo, float hi) {
    ull r; asm("mov.b64 %0, {%1, %2};" : "=l"(r) : "f"(lo), "f"(hi)); return r;
}
__device__ __forceinline__ float to_tf32(float x) {
    uint32_t u;
    asm("cvt.rna.tf32.f32 %0, %1;" : "=r"(u) : "f"(x));
    return __uint_as_float(u);
}
// m16n8k8 tf32 MMA (legacy warp-level path; base sm_103 target OK)
__device__ __forceinline__ void mma_tf32(float* d,
                                         float a0, float a1, float a2, float a3,
                                         float b0, float b1) {
    asm volatile(
        "mma.sync.aligned.m16n8k8.row.col.f32.tf32.tf32.f32 "
        "{%0,%1,%2,%3}, {%4,%5,%6,%7}, {%8,%9}, {%0,%1,%2,%3};"
        : "+f"(d[0]), "+f"(d[1]), "+f"(d[2]), "+f"(d[3])
        : "r"(__float_as_uint(a0)), "r"(__float_as_uint(a1)),
          "r"(__float_as_uint(a2)), "r"(__float_as_uint(a3)),
          "r"(__float_as_uint(b0)), "r"(__float_as_uint(b1)));
}

// ---------------------------------------------------------------------------
// Kernel 0: transpose w_ext[:,1:] -> g_Aprep[m][k], rounded to tf32 (rna)
// ---------------------------------------------------------------------------
__global__ void prepA_kernel(const float* __restrict__ w_ext)
{
    g_Aprep[blockIdx.x * C + threadIdx.x] =
        to_tf32(__ldg(&w_ext[(size_t)blockIdx.x * 257 + 1 + threadIdx.x]));
}

// ---------------------------------------------------------------------------
// Kernel 1: conv phase A, 4 channel-chunks for occupancy (960 blocks).
// Partial: g_G[b,chunk,j,p] = sum_{c in chunk} w_disp[c,j] * f[b,c,p]
// ---------------------------------------------------------------------------
#define CCH 64
__global__ __launch_bounds__(256) void convA_kernel(const float* __restrict__ f,
                                                    const float* __restrict__ w_disp)
{
    __shared__ ull sW2[CCH * 9];
    const int tid   = threadIdx.x;
    const int chunk = blockIdx.y;
    const int b     = blockIdx.z;
    const int p2    = blockIdx.x * 512 + tid * 2;

    for (int i = tid; i < CCH * 9; i += 256) {
        float w = __ldg(&w_disp[chunk * CCH * 9 + i]);
        sW2[i] = pack2(w, w);
    }
    __syncthreads();

    const float* Fb = f + (size_t)b * CHW + (size_t)chunk * CCH * HW;
    ull acc[9];
    #pragma unroll
    for (int j = 0; j < 9; j++) acc[j] = 0ull;

    #pragma unroll 4
    for (int c = 0; c < CCH; c++) {
        ull v = *(const ull*)&Fb[(size_t)c * HW + p2];
        #pragma unroll
        for (int j = 0; j < 9; j++) fma2(acc[j], sW2[c * 9 + j], v);
    }
    #pragma unroll
    for (int j = 0; j < 9; j++)
        *(ull*)&g_G[((size_t)((b * 4 + chunk) * 9 + j)) * HW + p2] = acc[j];
}

// ---------------------------------------------------------------------------
// Kernel 2: 3x3 combine (sum 4 partials), tanh -> disp, sampling params.
// ---------------------------------------------------------------------------
__global__ __launch_bounds__(256) void phaseB_kernel(const float* __restrict__ P2,
                                                     const float* __restrict__ b_disp)
{
    const int b = blockIdx.y;
    const int p = blockIdx.x * 256 + threadIdx.x;
    const int y = p / W, x = p % W;

    float s = 0.f;
    #pragma unroll
    for (int dy = -1; dy <= 1; dy++) {
        int yy = y + dy;
        if (yy < 0 || yy >= H) continue;
        #pragma unroll
        for (int dx = -1; dx <= 1; dx++) {
            int xx = x + dx;
            if (xx < 0 || xx >= W) continue;
            int j = (dy + 1) * 3 + (dx + 1);
            #pragma unroll
            for (int ch = 0; ch < 4; ch++)
                s += g_G[((size_t)((b * 4 + ch) * 9 + j)) * HW + yy * W + xx];
        }
    }
    const float dval = 0.1f * tanhf(s + __ldg(&b_disp[0]));

    const float fyv = __ldg(&P2[b * 12 + 5]) * 0.0625f;
    const float cyv = __ldg(&P2[b * 12 + 6]) * 0.0625f;
    const float Tyv = __ldg(&P2[b * 12 + 7]) * 0.0625f;
    const float denom = fabsf(fyv * 1.65f + Tyv) + 1e-10f;

    const float yf    = (float)y;
    const float ysb   = fmaxf(1.535f * (yf - cyv) / (2.f * (1.65f - 0.5f * 1.535f)), 0.f) * (1.f / 24.f);
    const float ybase = -1.f + yf * (2.f / 47.f);
    const float gy    = ybase + ysb + dval;

    float iy  = fminf(fmaxf((gy + 1.f) * 0.5f * 47.f, 0.f), 47.f);
    float y0f = floorf(iy);
    float wy  = iy - y0f;
    int y0 = (int)y0f;
    int y1 = min(y0 + 1, H - 1);

    const float sc = fyv * 0.54f / denom;
    float d0 = fmaxf(sc * (y0f - cyv), 0.f);
    float d1 = fmaxf(sc * ((float)y1 - cyv), 0.f);

    const int gi = b * HW + p;
    g_y0[gi]    = y0;
    g_wy[gi]    = wy;
    g_samp0[gi] = d0 + wy * (d1 - d0);
}

// ---------------------------------------------------------------------------
// Kernel 3: tf32 mma.sync GEMM, fused sample + epilogue.
// CTA: 128(o) x 128(px), K=256 in chunks of 32. 8 warps (2x4), warp tile
// 64x32: 4x4 m16n8k8 tiles, acc 64 regs. smem stride 136 -> conflict-free.
// ---------------------------------------------------------------------------
#define GM 128
#define GN 128
#define GK 32
#define SPAD 136
__global__ __launch_bounds__(256, 2) void gemm_mma_kernel(
    const float* __restrict__ f,
    const float* __restrict__ w_ext,
    const float* __restrict__ b_ext,
    const float* __restrict__ alpha,
    float* __restrict__ out)
{
    __shared__ float As[GK][SPAD];    // [k][m]
    __shared__ float Bs[GK][SPAD];    // [k][n]
    __shared__ int   sO0[GN], sO1[GN];
    __shared__ float sWy[GN], sSm[GN];

    const int tid  = threadIdx.x;
    const int warp = tid >> 5;
    const int lane = tid & 31;
    const int lg   = lane >> 2;       // group id 0..7
    const int lt   = lane & 3;        // thread-in-group 0..3
    const int wm   = (warp >> 2) * 64;    // warp m offset (0 / 64)
    const int wn   = (warp & 3) * 32;     // warp n offset (0..96)

    const int b  = blockIdx.z;
    const int m0 = blockIdx.y * GM;
    const int n0 = blockIdx.x * GN;
    const float* Fb = f + (size_t)b * CHW;

    if (tid < GN) {
        int p   = n0 + tid;
        int y0v = g_y0[b * HW + p];
        int x   = p % W;
        sO0[tid] = y0v * W + x;
        sO1[tid] = min(y0v + 1, H - 1) * W + x;
        sWy[tid] = g_wy[b * HW + p];
        sSm[tid] = g_samp0[b * HW + p];
    }

    float acc[4][4][4];
    #pragma unroll
    for (int mi = 0; mi < 4; mi++)
        #pragma unroll
        for (int nj = 0; nj < 4; nj++)
            #pragma unroll
            for (int t = 0; t < 4; t++) acc[mi][nj][t] = 0.f;

    for (int c = 0; c < C / GK; c++) {
        __syncthreads();   // protect smem reads of previous chunk

        // ---- A fill: g_Aprep[m0+m][c*32 + k] -> As[k][m] ----
        #pragma unroll
        for (int i = 0; i < 4; i++) {
            int e  = tid + i * 256;            // 1024 float4s
            int m  = e >> 3;
            int kq = (e & 7) * 4;
            float4 v = *(const float4*)(g_Aprep + (size_t)(m0 + m) * C + c * GK + kq);
            As[kq + 0][m] = v.x;
            As[kq + 1][m] = v.y;
            As[kq + 2][m] = v.z;
            As[kq + 3][m] = v.w;
        }
        // ---- B fill: sampled vertical lerp -> Bs[k][n], tf32-rounded ----
        #pragma unroll
        for (int i = 0; i < 16; i++) {
            int e = tid + i * 256;             // 4096 elements
            int k = e >> 7;
            int n = e & 127;
            const float* fk = Fb + (size_t)(c * GK + k) * HW;
            float v0 = __ldg(fk + sO0[n]);
            float v1 = __ldg(fk + sO1[n]);
            Bs[k][n] = to_tf32(fmaf(sWy[n], v1 - v0, v0));
        }
        __syncthreads();

        // ---- compute: 4 k8-steps ----
        #pragma unroll
        for (int ks = 0; ks < 4; ks++) {
            const int kb = ks * 8;
            float af[4][4];
            #pragma unroll
            for (int mi = 0; mi < 4; mi++) {
                int m = wm + mi * 16 + lg;
                af[mi][0] = As[kb + lt][m];
                af[mi][1] = As[kb + lt][m + 8];
                af[mi][2] = As[kb + lt + 4][m];
                af[mi][3] = As[kb + lt + 4][m + 8];
            }
            float bf[4][2];
            #pragma unroll
            for (int nj = 0; nj < 4; nj++) {
                int n = wn + nj * 8 + lg;
                bf[nj][0] = Bs[kb + lt][n];
                bf[nj][1] = Bs[kb + lt + 4][n];
            }
            #pragma unroll
            for (int mi = 0; mi < 4; mi++)
                #pragma unroll
                for (int nj = 0; nj < 4; nj++)
                    mma_tf32(acc[mi][nj],
                             af[mi][0], af[mi][1], af[mi][2], af[mi][3],
                             bf[nj][0], bf[nj][1]);
        }
    }

    // ---- fused epilogue ----
    const float al = __ldg(&alpha[0]);
    #pragma unroll
    for (int mi = 0; mi < 4; mi++) {
        const int r0 = m0 + wm + mi * 16 + lg;    // rows r0, r0+8
        const float w0a = __ldg(&w_ext[(size_t)r0 * 257]);
        const float bea = __ldg(&b_ext[r0]);
        const float w0b = __ldg(&w_ext[(size_t)(r0 + 8) * 257]);
        const float beb = __ldg(&b_ext[r0 + 8]);
        #pragma unroll
        for (int nj = 0; nj < 4; nj++) {
            const int cl  = wn + nj * 8 + 2 * lt;       // local col (even)
            const int col = n0 + cl;
            const float s0 = sSm[cl], s1 = sSm[cl + 1];

            size_t oa = ((size_t)b * C + r0) * HW + col;
            size_t ob = oa + (size_t)8 * HW;

            float2 fa = *(const float2*)(f + oa);
            float2 fb = *(const float2*)(f + ob);
            float2 ra, rb;
            ra.x = fmaxf(fa.x + al * (acc[mi][nj][0] + w0a * s0 + bea), 0.f);
            ra.y = fmaxf(fa.y + al * (acc[mi][nj][1] + w0a * s1 + bea), 0.f);
            rb.x = fmaxf(fb.x + al * (acc[mi][nj][2] + w0b * s0 + beb), 0.f);
            rb.y = fmaxf(fb.y + al * (acc[mi][nj][3] + w0b * s1 + beb), 0.f);
            *(float2*)(out + oa) = ra;
            *(float2*)(out + ob) = rb;
        }
    }
}

// ---------------------------------------------------------------------------
extern "C" void kernel_launch(void* const* d_in, const int* in_sizes, int n_in,
                              void* d_out, int out_size)
{
    const float* features = (const float*)d_in[0];
    const float* P2       = (const float*)d_in[1];
    const float* w_disp   = (const float*)d_in[2];
    const float* b_disp   = (const float*)d_in[3];
    const float* w_ext    = (const float*)d_in[4];
    const float* b_ext    = (const float*)d_in[5];
    const float* alpha    = (const float*)d_in[6];
    float* out = (float*)d_out;

    prepA_kernel <<<C, C>>>(w_ext);
    convA_kernel <<<dim3(HW / 512, 4, Bz), 256>>>(features, w_disp);
    phaseB_kernel<<<dim3(HW / 256, Bz), 256>>>(P2, b_disp);
    gemm_mma_kernel<<<dim3(HW / GN, C / GM, Bz), 256>>>(
        features, w_ext, b_ext, alpha, out);
}

// round 7
// speedup vs baseline: 3.4949x; 1.6335x over previous
#include <cuda_runtime.h>
#include <math.h>
#include <stdint.h>

#define Bz 16
#define C 256
#define H 48
#define W 160
#define HW (H*W)            // 7680
#define CHW (C*HW)          // 1966080

typedef unsigned long long ull;

// Scratch (__device__ globals; no allocations allowed)
__device__ float g_G[(size_t)Bz * 4 * 9 * HW];   // partial conv reductions
__device__ int   g_y0[Bz * HW];
__device__ float g_wy[Bz * HW];
__device__ float g_samp0[Bz * HW];
__device__ float g_Aprep[C * C];                 // transposed w_ext[:,1:], tf32-rounded

// ===================== PTX helpers ==============================
__device__ __forceinline__ void fma2(ull& d, ull a, ull b) {
    asm("fma.rn.f32x2 %0, %1, %2, %0;" : "+l"(d) : "l"(a), "l"(b));
}
__device__ __forceinline__ ull pack2(float lo, float hi) {
    ull r; asm("mov.b64 %0, {%1, %2};" : "=l"(r) : "f"(lo), "f"(hi)); return r;
}
__device__ __forceinline__ float to_tf32(float x) {
    uint32_t u;
    asm("cvt.rna.tf32.f32 %0, %1;" : "=r"(u) : "f"(x));
    return __uint_as_float(u);
}
__device__ __forceinline__ uint32_t smem_u32(const void* p) {
    uint32_t a;
    asm("{ .reg .u64 t; cvta.to.shared.u64 t, %1; cvt.u32.u64 %0, t; }" : "=r"(a) : "l"(p));
    return a;
}
#define CP_ASYNC_4(dst, src) \
    asm volatile("cp.async.ca.shared.global [%0], [%1], 4;" :: "r"(dst), "l"(src))
#define CP_ASYNC_16(dst, src) \
    asm volatile("cp.async.cg.shared.global [%0], [%1], 16;" :: "r"(dst), "l"(src))
#define CP_COMMIT() asm volatile("cp.async.commit_group;" ::: "memory")
#define CP_WAIT(n)  asm volatile("cp.async.wait_group %0;" :: "n"(n) : "memory")

// m16n8k8 tf32 MMA (base sm_103 target OK)
__device__ __forceinline__ void mma_tf32(float* d,
                                         float a0, float a1, float a2, float a3,
                                         float b0, float b1) {
    asm volatile(
        "mma.sync.aligned.m16n8k8.row.col.f32.tf32.tf32.f32 "
        "{%0,%1,%2,%3}, {%4,%5,%6,%7}, {%8,%9}, {%0,%1,%2,%3};"
        : "+f"(d[0]), "+f"(d[1]), "+f"(d[2]), "+f"(d[3])
        : "r"(__float_as_uint(a0)), "r"(__float_as_uint(a1)),
          "r"(__float_as_uint(a2)), "r"(__float_as_uint(a3)),
          "r"(__float_as_uint(b0)), "r"(__float_as_uint(b1)));
}

// ---------------------------------------------------------------------------
// Kernel 0: transpose w_ext[:,1:] -> g_Aprep[m][k], rounded to tf32 (rna)
// ---------------------------------------------------------------------------
__global__ void prepA_kernel(const float* __restrict__ w_ext)
{
    g_Aprep[blockIdx.x * C + threadIdx.x] =
        to_tf32(__ldg(&w_ext[(size_t)blockIdx.x * 257 + 1 + threadIdx.x]));
}

// ---------------------------------------------------------------------------
// Kernel 1: conv phase A, 4 channel-chunks (960 blocks).
// ---------------------------------------------------------------------------
#define CCH 64
__global__ __launch_bounds__(256) void convA_kernel(const float* __restrict__ f,
                                                    const float* __restrict__ w_disp)
{
    __shared__ ull sW2[CCH * 9];
    const int tid   = threadIdx.x;
    const int chunk = blockIdx.y;
    const int b     = blockIdx.z;
    const int p2    = blockIdx.x * 512 + tid * 2;

    for (int i = tid; i < CCH * 9; i += 256) {
        float w = __ldg(&w_disp[chunk * CCH * 9 + i]);
        sW2[i] = pack2(w, w);
    }
    __syncthreads();

    const float* Fb = f + (size_t)b * CHW + (size_t)chunk * CCH * HW;
    ull acc[9];
    #pragma unroll
    for (int j = 0; j < 9; j++) acc[j] = 0ull;

    #pragma unroll 4
    for (int c = 0; c < CCH; c++) {
        ull v = *(const ull*)&Fb[(size_t)c * HW + p2];
        #pragma unroll
        for (int j = 0; j < 9; j++) fma2(acc[j], sW2[c * 9 + j], v);
    }
    #pragma unroll
    for (int j = 0; j < 9; j++)
        *(ull*)&g_G[((size_t)((b * 4 + chunk) * 9 + j)) * HW + p2] = acc[j];
}

// ---------------------------------------------------------------------------
// Kernel 2: 3x3 combine, tanh -> disp, sampling params.
// ---------------------------------------------------------------------------
__global__ __launch_bounds__(256) void phaseB_kernel(const float* __restrict__ P2,
                                                     const float* __restrict__ b_disp)
{
    const int b = blockIdx.y;
    const int p = blockIdx.x * 256 + threadIdx.x;
    const int y = p / W, x = p % W;

    float s = 0.f;
    #pragma unroll
    for (int dy = -1; dy <= 1; dy++) {
        int yy = y + dy;
        if (yy < 0 || yy >= H) continue;
        #pragma unroll
        for (int dx = -1; dx <= 1; dx++) {
            int xx = x + dx;
            if (xx < 0 || xx >= W) continue;
            int j = (dy + 1) * 3 + (dx + 1);
            #pragma unroll
            for (int ch = 0; ch < 4; ch++)
                s += g_G[((size_t)((b * 4 + ch) * 9 + j)) * HW + yy * W + xx];
        }
    }
    const float dval = 0.1f * tanhf(s + __ldg(&b_disp[0]));

    const float fyv = __ldg(&P2[b * 12 + 5]) * 0.0625f;
    const float cyv = __ldg(&P2[b * 12 + 6]) * 0.0625f;
    const float Tyv = __ldg(&P2[b * 12 + 7]) * 0.0625f;
    const float denom = fabsf(fyv * 1.65f + Tyv) + 1e-10f;

    const float yf    = (float)y;
    const float ysb   = fmaxf(1.535f * (yf - cyv) / (2.f * (1.65f - 0.5f * 1.535f)), 0.f) * (1.f / 24.f);
    const float ybase = -1.f + yf * (2.f / 47.f);
    const float gy    = ybase + ysb + dval;

    float iy  = fminf(fmaxf((gy + 1.f) * 0.5f * 47.f, 0.f), 47.f);
    float y0f = floorf(iy);
    float wy  = iy - y0f;
    int y0 = (int)y0f;
    int y1 = min(y0 + 1, H - 1);

    const float sc = fyv * 0.54f / denom;
    float d0 = fmaxf(sc * (y0f - cyv), 0.f);
    float d1 = fmaxf(sc * ((float)y1 - cyv), 0.f);

    const int gi = b * HW + p;
    g_y0[gi]    = y0;
    g_wy[gi]    = wy;
    g_samp0[gi] = d0 + wy * (d1 - d0);
}

// ---------------------------------------------------------------------------
// Kernel 3: tf32 mma.sync GEMM, cp.async double-buffered, fused epilogue.
// CTA 128(o) x 128(px), K chunks of 32. Raw v0/v1 taps in smem; lerp+tf32 at
// fragment load. A [m][k] stride 36, B [k][n] stride 132 (conflict-free).
// ---------------------------------------------------------------------------
#define GM 128
#define GN 128
#define GK 32
#define ASTR 36
#define BSTR 132
#define ABUF  (GM * ASTR * 4)           // 18432 B
#define BBUF  (GK * BSTR * 4)           // 16896 B
#define OFF_A   0
#define OFF_V0  (2 * ABUF)              // 36864
#define OFF_V1  (OFF_V0 + 2 * BBUF)     // 70656
#define OFF_CTL (OFF_V1 + 2 * BBUF)     // 104448
#define SMEM_TOT (OFF_CTL + 2048)       // 106496

__global__ __launch_bounds__(256, 2) void gemm_mma_kernel(
    const float* __restrict__ f,
    const float* __restrict__ w_ext,
    const float* __restrict__ b_ext,
    const float* __restrict__ alpha,
    float* __restrict__ out)
{
    extern __shared__ __align__(16) char smem[];
    const uint32_t sb = smem_u32(smem);

    int*   sO0 = (int*)  (smem + OFF_CTL);
    int*   sO1 = (int*)  (smem + OFF_CTL + 512);
    float* sWy = (float*)(smem + OFF_CTL + 1024);
    float* sSm = (float*)(smem + OFF_CTL + 1536);

    const int tid  = threadIdx.x;
    const int warp = tid >> 5;
    const int lane = tid & 31;
    const int lg   = lane >> 2;
    const int lt   = lane & 3;
    const int wm   = (warp >> 2) * 64;
    const int wn   = (warp & 3) * 32;

    const int b  = blockIdx.z;
    const int m0 = blockIdx.y * GM;
    const int n0 = blockIdx.x * GN;
    const float* Fb = f + (size_t)b * CHW;

    if (tid < GN) {
        int p   = n0 + tid;
        int y0v = g_y0[b * HW + p];
        int x   = p % W;
        sO0[tid] = y0v * W + x;
        sO1[tid] = min(y0v + 1, H - 1) * W + x;
        sWy[tid] = g_wy[b * HW + p];
        sSm[tid] = g_samp0[b * HW + p];
    }
    __syncthreads();

    // ---- async prefetch of one K-chunk into buffer `buf` ----
    auto prefetch = [&](int c, int buf) {
        const uint32_t ab  = sb + OFF_A  + buf * ABUF;
        const uint32_t v0b = sb + OFF_V0 + buf * BBUF;
        const uint32_t v1b = sb + OFF_V1 + buf * BBUF;
        #pragma unroll
        for (int i = 0; i < 4; i++) {
            int e  = tid + i * 256;           // 1024 float4s of A
            int m  = e >> 3;
            int kq = e & 7;
            const float* src = g_Aprep + (size_t)(m0 + m) * C + c * GK + kq * 4;
            CP_ASYNC_16(ab + m * (ASTR * 4) + kq * 16, src);
        }
        #pragma unroll
        for (int i = 0; i < 16; i++) {
            int e = tid + i * 256;            // 4096 B elements
            int k = e >> 7;
            int n = e & 127;
            const float* fk = Fb + (size_t)(c * GK + k) * HW;
            uint32_t doff = (k * BSTR + n) * 4;
            CP_ASYNC_4(v0b + doff, fk + sO0[n]);
            CP_ASYNC_4(v1b + doff, fk + sO1[n]);
        }
        CP_COMMIT();
    };

    float acc[4][4][4];
    #pragma unroll
    for (int mi = 0; mi < 4; mi++)
        #pragma unroll
        for (int nj = 0; nj < 4; nj++)
            #pragma unroll
            for (int t = 0; t < 4; t++) acc[mi][nj][t] = 0.f;

    float wv[4];
    #pragma unroll
    for (int nj = 0; nj < 4; nj++) wv[nj] = sWy[wn + nj * 8 + lg];

    prefetch(0, 0);
    prefetch(1, 1);

    for (int c = 0; c < C / GK; c++) {
        const int buf = c & 1;
        if (c < C / GK - 1) CP_WAIT(1); else CP_WAIT(0);
        __syncthreads();

        const float* Af = (const float*)(smem + OFF_A  + buf * ABUF);
        const float* V0 = (const float*)(smem + OFF_V0 + buf * BBUF);
        const float* V1 = (const float*)(smem + OFF_V1 + buf * BBUF);

        #pragma unroll
        for (int ks = 0; ks < 4; ks++) {
            const int kb = ks * 8;
            float af[4][4];
            #pragma unroll
            for (int mi = 0; mi < 4; mi++) {
                int m = wm + mi * 16 + lg;
                af[mi][0] = Af[m * ASTR + kb + lt];
                af[mi][1] = Af[(m + 8) * ASTR + kb + lt];
                af[mi][2] = Af[m * ASTR + kb + lt + 4];
                af[mi][3] = Af[(m + 8) * ASTR + kb + lt + 4];
            }
            float bf[4][2];
            #pragma unroll
            for (int nj = 0; nj < 4; nj++) {
                int n   = wn + nj * 8 + lg;
                int i0  = (kb + lt) * BSTR + n;
                int i1  = (kb + lt + 4) * BSTR + n;
                float a0 = V0[i0], b0v = V1[i0];
                float a1 = V0[i1], b1v = V1[i1];
                bf[nj][0] = to_tf32(fmaf(wv[nj], b0v - a0, a0));
                bf[nj][1] = to_tf32(fmaf(wv[nj], b1v - a1, a1));
            }
            #pragma unroll
            for (int mi = 0; mi < 4; mi++)
                #pragma unroll
                for (int nj = 0; nj < 4; nj++)
                    mma_tf32(acc[mi][nj],
                             af[mi][0], af[mi][1], af[mi][2], af[mi][3],
                             bf[nj][0], bf[nj][1]);
        }
        __syncthreads();
        if (c + 2 < C / GK) prefetch(c + 2, buf);
    }

    // ---- fused epilogue ----
    const float al = __ldg(&alpha[0]);
    #pragma unroll
    for (int mi = 0; mi < 4; mi++) {
        const int r0 = m0 + wm + mi * 16 + lg;
        const float w0a = __ldg(&w_ext[(size_t)r0 * 257]);
        const float bea = __ldg(&b_ext[r0]);
        const float w0b = __ldg(&w_ext[(size_t)(r0 + 8) * 257]);
        const float beb = __ldg(&b_ext[r0 + 8]);
        #pragma unroll
        for (int nj = 0; nj < 4; nj++) {
            const int cl  = wn + nj * 8 + 2 * lt;
            const int col = n0 + cl;
            const float s0 = sSm[cl], s1 = sSm[cl + 1];

            size_t oa = ((size_t)b * C + r0) * HW + col;
            size_t ob = oa + (size_t)8 * HW;

            float2 fa = *(const float2*)(f + oa);
            float2 fb = *(const float2*)(f + ob);
            float2 ra, rb;
            ra.x = fmaxf(fa.x + al * (acc[mi][nj][0] + w0a * s0 + bea), 0.f);
            ra.y = fmaxf(fa.y + al * (acc[mi][nj][1] + w0a * s1 + bea), 0.f);
            rb.x = fmaxf(fb.x + al * (acc[mi][nj][2] + w0b * s0 + beb), 0.f);
            rb.y = fmaxf(fb.y + al * (acc[mi][nj][3] + w0b * s1 + beb), 0.f);
            *(float2*)(out + oa) = ra;
            *(float2*)(out + ob) = rb;
        }
    }
}

// ---------------------------------------------------------------------------
extern "C" void kernel_launch(void* const* d_in, const int* in_sizes, int n_in,
                              void* d_out, int out_size)
{
    const float* features = (const float*)d_in[0];
    const float* P2       = (const float*)d_in[1];
    const float* w_disp   = (const float*)d_in[2];
    const float* b_disp   = (const float*)d_in[3];
    const float* w_ext    = (const float*)d_in[4];
    const float* b_ext    = (const float*)d_in[5];
    const float* alpha    = (const float*)d_in[6];
    float* out = (float*)d_out;

    static int attr_set = 0;
    if (!attr_set) {
        cudaFuncSetAttribute(gemm_mma_kernel,
                             cudaFuncAttributeMaxDynamicSharedMemorySize, SMEM_TOT);
        attr_set = 1;
    }

    prepA_kernel <<<C, C>>>(w_ext);
    convA_kernel <<<dim3(HW / 512, 4, Bz), 256>>>(features, w_disp);
    phaseB_kernel<<<dim3(HW / 256, Bz), 256>>>(P2, b_disp);
    gemm_mma_kernel<<<dim3(HW / GN, C / GM, Bz), 256, SMEM_TOT>>>(
        features, w_ext, b_ext, alpha, out);
}

// round 8
// speedup vs baseline: 4.0251x; 1.1517x over previous
#include <cuda_runtime.h>
#include <math.h>
#include <stdint.h>

#define Bz 16
#define C 256
#define H 48
#define W 160
#define HW (H*W)            // 7680
#define CHW (C*HW)          // 1966080

typedef unsigned long long ull;

// Scratch (__device__ globals; no allocations allowed)
__device__ float g_G[(size_t)Bz * 4 * 9 * HW];   // partial conv reductions
__device__ int   g_y0[Bz * HW];
__device__ float g_wy[Bz * HW];
__device__ float g_samp0[Bz * HW];
__device__ float g_Aprep[C * C];                 // transposed w_ext[:,1:], tf32-rounded

// ===================== PTX helpers ==============================
__device__ __forceinline__ void fma2(ull& d, ull a, ull b) {
    asm("fma.rn.f32x2 %0, %1, %2, %0;" : "+l"(d) : "l"(a), "l"(b));
}
__device__ __forceinline__ ull pack2(float lo, float hi) {
    ull r; asm("mov.b64 %0, {%1, %2};" : "=l"(r) : "f"(lo), "f"(hi)); return r;
}
__device__ __forceinline__ float to_tf32(float x) {
    uint32_t u;
    asm("cvt.rna.tf32.f32 %0, %1;" : "=r"(u) : "f"(x));
    return __uint_as_float(u);
}
__device__ __forceinline__ uint32_t smem_u32(const void* p) {
    uint32_t a;
    asm("{ .reg .u64 t; cvta.to.shared.u64 t, %1; cvt.u32.u64 %0, t; }" : "=r"(a) : "l"(p));
    return a;
}
#define CP_ASYNC_4(dst, src) \
    asm volatile("cp.async.ca.shared.global [%0], [%1], 4;" :: "r"(dst), "l"(src))
#define CP_ASYNC_16(dst, src) \
    asm volatile("cp.async.cg.shared.global [%0], [%1], 16;" :: "r"(dst), "l"(src))
#define CP_COMMIT() asm volatile("cp.async.commit_group;" ::: "memory")
#define CP_WAIT(n)  asm volatile("cp.async.wait_group %0;" :: "n"(n) : "memory")

// m16n8k8 tf32 MMA (base sm_103 target OK)
__device__ __forceinline__ void mma_tf32(float* d,
                                         float a0, float a1, float a2, float a3,
                                         float b0, float b1) {
    asm volatile(
        "mma.sync.aligned.m16n8k8.row.col.f32.tf32.tf32.f32 "
        "{%0,%1,%2,%3}, {%4,%5,%6,%7}, {%8,%9}, {%0,%1,%2,%3};"
        : "+f"(d[0]), "+f"(d[1]), "+f"(d[2]), "+f"(d[3])
        : "r"(__float_as_uint(a0)), "r"(__float_as_uint(a1)),
          "r"(__float_as_uint(a2)), "r"(__float_as_uint(a3)),
          "r"(__float_as_uint(b0)), "r"(__float_as_uint(b1)));
}

// ---------------------------------------------------------------------------
// Kernel 0: transpose w_ext[:,1:] -> g_Aprep[m][k], rounded to tf32 (rna)
// ---------------------------------------------------------------------------
__global__ void prepA_kernel(const float* __restrict__ w_ext)
{
    g_Aprep[blockIdx.x * C + threadIdx.x] =
        to_tf32(__ldg(&w_ext[(size_t)blockIdx.x * 257 + 1 + threadIdx.x]));
}

// ---------------------------------------------------------------------------
// Kernel 1: conv phase A, 4 channel-chunks (960 blocks).
// ---------------------------------------------------------------------------
#define CCH 64
__global__ __launch_bounds__(256) void convA_kernel(const float* __restrict__ f,
                                                    const float* __restrict__ w_disp)
{
    __shared__ ull sW2[CCH * 9];
    const int tid   = threadIdx.x;
    const int chunk = blockIdx.y;
    const int b     = blockIdx.z;
    const int p2    = blockIdx.x * 512 + tid * 2;

    for (int i = tid; i < CCH * 9; i += 256) {
        float w = __ldg(&w_disp[chunk * CCH * 9 + i]);
        sW2[i] = pack2(w, w);
    }
    __syncthreads();

    const float* Fb = f + (size_t)b * CHW + (size_t)chunk * CCH * HW;
    ull acc[9];
    #pragma unroll
    for (int j = 0; j < 9; j++) acc[j] = 0ull;

    #pragma unroll 4
    for (int c = 0; c < CCH; c++) {
        ull v = *(const ull*)&Fb[(size_t)c * HW + p2];
        #pragma unroll
        for (int j = 0; j < 9; j++) fma2(acc[j], sW2[c * 9 + j], v);
    }
    #pragma unroll
    for (int j = 0; j < 9; j++)
        *(ull*)&g_G[((size_t)((b * 4 + chunk) * 9 + j)) * HW + p2] = acc[j];
}

// ---------------------------------------------------------------------------
// Kernel 2: 3x3 combine, tanh -> disp, sampling params.
// ---------------------------------------------------------------------------
__global__ __launch_bounds__(256) void phaseB_kernel(const float* __restrict__ P2,
                                                     const float* __restrict__ b_disp)
{
    const int b = blockIdx.y;
    const int p = blockIdx.x * 256 + threadIdx.x;
    const int y = p / W, x = p % W;

    float s = 0.f;
    #pragma unroll
    for (int dy = -1; dy <= 1; dy++) {
        int yy = y + dy;
        if (yy < 0 || yy >= H) continue;
        #pragma unroll
        for (int dx = -1; dx <= 1; dx++) {
            int xx = x + dx;
            if (xx < 0 || xx >= W) continue;
            int j = (dy + 1) * 3 + (dx + 1);
            #pragma unroll
            for (int ch = 0; ch < 4; ch++)
                s += g_G[((size_t)((b * 4 + ch) * 9 + j)) * HW + yy * W + xx];
        }
    }
    const float dval = 0.1f * tanhf(s + __ldg(&b_disp[0]));

    const float fyv = __ldg(&P2[b * 12 + 5]) * 0.0625f;
    const float cyv = __ldg(&P2[b * 12 + 6]) * 0.0625f;
    const float Tyv = __ldg(&P2[b * 12 + 7]) * 0.0625f;
    const float denom = fabsf(fyv * 1.65f + Tyv) + 1e-10f;

    const float yf    = (float)y;
    const float ysb   = fmaxf(1.535f * (yf - cyv) / (2.f * (1.65f - 0.5f * 1.535f)), 0.f) * (1.f / 24.f);
    const float ybase = -1.f + yf * (2.f / 47.f);
    const float gy    = ybase + ysb + dval;

    float iy  = fminf(fmaxf((gy + 1.f) * 0.5f * 47.f, 0.f), 47.f);
    float y0f = floorf(iy);
    float wy  = iy - y0f;
    int y0 = (int)y0f;
    int y1 = min(y0 + 1, H - 1);

    const float sc = fyv * 0.54f / denom;
    float d0 = fmaxf(sc * (y0f - cyv), 0.f);
    float d1 = fmaxf(sc * ((float)y1 - cyv), 0.f);

    const int gi = b * HW + p;
    g_y0[gi]    = y0;
    g_wy[gi]    = wy;
    g_samp0[gi] = d0 + wy * (d1 - d0);
}

// ---------------------------------------------------------------------------
// Kernel 3: tf32 mma.sync GEMM, cp.async double-buffered, fused epilogue.
// CTA covers ALL 256 out-channels x 128 px (taps loaded ONCE per pixel tile),
// 512 threads, 16 warps (4x4), warp tile 64x32. K chunks of 32.
// Raw v0/v1 taps in smem; lerp+tf32 at fragment load.
// ---------------------------------------------------------------------------
#define GM 256
#define GN 128
#define GK 32
#define ASTR 36
#define BSTR 132
#define ABUF  (GM * ASTR * 4)           // 36864 B
#define BBUF  (GK * BSTR * 4)           // 16896 B
#define OFF_A   0
#define OFF_V0  (2 * ABUF)              // 73728
#define OFF_V1  (OFF_V0 + 2 * BBUF)     // 107520
#define OFF_CTL (OFF_V1 + 2 * BBUF)     // 141312
#define SMEM_TOT (OFF_CTL + 2048)       // 143360

__global__ __launch_bounds__(512, 1) void gemm_mma_kernel(
    const float* __restrict__ f,
    const float* __restrict__ w_ext,
    const float* __restrict__ b_ext,
    const float* __restrict__ alpha,
    float* __restrict__ out)
{
    extern __shared__ __align__(16) char smem[];
    const uint32_t sb = smem_u32(smem);

    int*   sO0 = (int*)  (smem + OFF_CTL);
    int*   sO1 = (int*)  (smem + OFF_CTL + 512);
    float* sWy = (float*)(smem + OFF_CTL + 1024);
    float* sSm = (float*)(smem + OFF_CTL + 1536);

    const int tid  = threadIdx.x;
    const int warp = tid >> 5;
    const int lane = tid & 31;
    const int lg   = lane >> 2;
    const int lt   = lane & 3;
    const int wm   = (warp >> 2) * 64;     // 0,64,128,192
    const int wn   = (warp & 3) * 32;      // 0..96

    const int b  = blockIdx.z;
    const int n0 = blockIdx.x * GN;
    const float* Fb = f + (size_t)b * CHW;

    if (tid < GN) {
        int p   = n0 + tid;
        int y0v = g_y0[b * HW + p];
        int x   = p % W;
        sO0[tid] = y0v * W + x;
        sO1[tid] = min(y0v + 1, H - 1) * W + x;
        sWy[tid] = g_wy[b * HW + p];
        sSm[tid] = g_samp0[b * HW + p];
    }
    __syncthreads();

    // ---- async prefetch of one K-chunk into buffer `buf` ----
    auto prefetch = [&](int c, int buf) {
        const uint32_t ab  = sb + OFF_A  + buf * ABUF;
        const uint32_t v0b = sb + OFF_V0 + buf * BBUF;
        const uint32_t v1b = sb + OFF_V1 + buf * BBUF;
        #pragma unroll
        for (int i = 0; i < 4; i++) {
            int e  = tid + i * 512;           // 2048 float4s of A (256 m x 8)
            int m  = e >> 3;
            int kq = e & 7;
            const float* src = g_Aprep + (size_t)m * C + c * GK + kq * 4;
            CP_ASYNC_16(ab + m * (ASTR * 4) + kq * 16, src);
        }
        #pragma unroll
        for (int i = 0; i < 8; i++) {
            int e = tid + i * 512;            // 4096 B positions
            int k = e >> 7;
            int n = e & 127;
            const float* fk = Fb + (size_t)(c * GK + k) * HW;
            uint32_t doff = (k * BSTR + n) * 4;
            CP_ASYNC_4(v0b + doff, fk + sO0[n]);
            CP_ASYNC_4(v1b + doff, fk + sO1[n]);
        }
        CP_COMMIT();
    };

    float acc[4][4][4];
    #pragma unroll
    for (int mi = 0; mi < 4; mi++)
        #pragma unroll
        for (int nj = 0; nj < 4; nj++)
            #pragma unroll
            for (int t = 0; t < 4; t++) acc[mi][nj][t] = 0.f;

    float wv[4];
    #pragma unroll
    for (int nj = 0; nj < 4; nj++) wv[nj] = sWy[wn + nj * 8 + lg];

    prefetch(0, 0);
    prefetch(1, 1);

    for (int c = 0; c < C / GK; c++) {
        const int buf = c & 1;
        if (c < C / GK - 1) CP_WAIT(1); else CP_WAIT(0);
        __syncthreads();

        const float* Af = (const float*)(smem + OFF_A  + buf * ABUF);
        const float* V0 = (const float*)(smem + OFF_V0 + buf * BBUF);
        const float* V1 = (const float*)(smem + OFF_V1 + buf * BBUF);

        #pragma unroll
        for (int ks = 0; ks < 4; ks++) {
            const int kb = ks * 8;
            float af[4][4];
            #pragma unroll
            for (int mi = 0; mi < 4; mi++) {
                int m = wm + mi * 16 + lg;
                af[mi][0] = Af[m * ASTR + kb + lt];
                af[mi][1] = Af[(m + 8) * ASTR + kb + lt];
                af[mi][2] = Af[m * ASTR + kb + lt + 4];
                af[mi][3] = Af[(m + 8) * ASTR + kb + lt + 4];
            }
            float bf[4][2];
            #pragma unroll
            for (int nj = 0; nj < 4; nj++) {
                int n   = wn + nj * 8 + lg;
                int i0  = (kb + lt) * BSTR + n;
                int i1  = (kb + lt + 4) * BSTR + n;
                float a0 = V0[i0], b0v = V1[i0];
                float a1 = V0[i1], b1v = V1[i1];
                bf[nj][0] = to_tf32(fmaf(wv[nj], b0v - a0, a0));
                bf[nj][1] = to_tf32(fmaf(wv[nj], b1v - a1, a1));
            }
            #pragma unroll
            for (int mi = 0; mi < 4; mi++)
                #pragma unroll
                for (int nj = 0; nj < 4; nj++)
                    mma_tf32(acc[mi][nj],
                             af[mi][0], af[mi][1], af[mi][2], af[mi][3],
                             bf[nj][0], bf[nj][1]);
        }
        __syncthreads();
        if (c + 2 < C / GK) prefetch(c + 2, buf);
    }

    // ---- fused epilogue ----
    const float al = __ldg(&alpha[0]);
    #pragma unroll
    for (int mi = 0; mi < 4; mi++) {
        const int r0 = wm + mi * 16 + lg;
        const float w0a = __ldg(&w_ext[(size_t)r0 * 257]);
        const float bea = __ldg(&b_ext[r0]);
        const float w0b = __ldg(&w_ext[(size_t)(r0 + 8) * 257]);
        const float beb = __ldg(&b_ext[r0 + 8]);
        #pragma unroll
        for (int nj = 0; nj < 4; nj++) {
            const int cl  = wn + nj * 8 + 2 * lt;
            const int col = n0 + cl;
            const float s0 = sSm[cl], s1 = sSm[cl + 1];

            size_t oa = ((size_t)b * C + r0) * HW + col;
            size_t ob = oa + (size_t)8 * HW;

            float2 fa = *(const float2*)(f + oa);
            float2 fb = *(const float2*)(f + ob);
            float2 ra, rb;
            ra.x = fmaxf(fa.x + al * (acc[mi][nj][0] + w0a * s0 + bea), 0.f);
            ra.y = fmaxf(fa.y + al * (acc[mi][nj][1] + w0a * s1 + bea), 0.f);
            rb.x = fmaxf(fb.x + al * (acc[mi][nj][2] + w0b * s0 + beb), 0.f);
            rb.y = fmaxf(fb.y + al * (acc[mi][nj][3] + w0b * s1 + beb), 0.f);
            *(float2*)(out + oa) = ra;
            *(float2*)(out + ob) = rb;
        }
    }
}

// ---------------------------------------------------------------------------
extern "C" void kernel_launch(void* const* d_in, const int* in_sizes, int n_in,
                              void* d_out, int out_size)
{
    const float* features = (const float*)d_in[0];
    const float* P2       = (const float*)d_in[1];
    const float* w_disp   = (const float*)d_in[2];
    const float* b_disp   = (const float*)d_in[3];
    const float* w_ext    = (const float*)d_in[4];
    const float* b_ext    = (const float*)d_in[5];
    const float* alpha    = (const float*)d_in[6];
    float* out = (float*)d_out;

    cudaFuncSetAttribute(gemm_mma_kernel,
                         cudaFuncAttributeMaxDynamicSharedMemorySize, SMEM_TOT);

    prepA_kernel <<<C, C>>>(w_ext);
    convA_kernel <<<dim3(HW / 512, 4, Bz), 256>>>(features, w_disp);
    phaseB_kernel<<<dim3(HW / 256, Bz), 256>>>(P2, b_disp);
    gemm_mma_kernel<<<dim3(HW / GN, 1, Bz), 512, SMEM_TOT>>>(
        features, w_ext, b_ext, alpha, out);
}